// round 7
// baseline (speedup 1.0000x reference)
#include <cuda_runtime.h>
#include <cuda_bf16.h>

// Problem constants
#define N1M1 4096          // row width of b / y
#define ROWS 8191          // n2 - 1 rows contribute
#define THREADS 256
#define GBLOCKS 1184       // 148 SMs * 8 CTAs -> single wave

__device__ float        g_partials[GBLOCKS];
__device__ unsigned int g_count = 0;

__global__ __launch_bounds__(THREADS)
void rosen_fused_kernel(const float* __restrict__ x,
                        const float* __restrict__ a,
                        const float* __restrict__ b,
                        const float* __restrict__ mu,
                        float* __restrict__ out)
{
    const int tid  = threadIdx.x;
    const int lane = tid & 31;
    const int wid  = tid >> 5;
    const int j0   = tid << 4;          // 16 floats per thread; covers the 4096-wide row
    const bool is_first = (tid == 0);
    const bool is_last  = (tid == THREADS - 1);

    float sum = 0.0f;

    // One full row per block-iteration: ~10 independent loads batched up front.
    for (int i = blockIdx.x; i < ROWS; i += GBLOCKS) {
        const long   base = (long)i * N1M1;
        const float* xr   = x + base + j0;
        const float* br   = b + base + j0;

        // Front-batched loads (high MLP_p1). x16 doubles as the roll-wrap value:
        // for tid==0 we need x[base+4096]; for everyone else x[base+j0+16].
        const float4 xv0 = __ldcs(reinterpret_cast<const float4*>(xr));
        const float4 xv1 = __ldcs(reinterpret_cast<const float4*>(xr + 4));
        const float4 xv2 = __ldcs(reinterpret_cast<const float4*>(xr + 8));
        const float4 xv3 = __ldcs(reinterpret_cast<const float4*>(xr + 12));
        const float  x16  = __ldcs(xr + 16);                    // <= base+4096, valid
        const float  xwrp = __ldcs(x + base + (is_first ? N1M1 : j0)); // tid0: wrap val; else dup of xv0.x (L1 hit)
        const float4 b0 = __ldcs(reinterpret_cast<const float4*>(br));
        const float4 b1 = __ldcs(reinterpret_cast<const float4*>(br + 4));
        const float4 b2 = __ldcs(reinterpret_cast<const float4*>(br + 8));
        const float4 b3 = __ldcs(reinterpret_cast<const float4*>(br + 12));

        const float p0  = is_first ? xwrp : xv0.x;   // roll wrap: y_prev[i,0] = x[base+4096]
        const float w14 = is_last ? 0.0f : b3.z;     // columns 4094,4095 don't contribute
        const float w15 = is_last ? 0.0f : b3.w;

        float d;
        d = xv0.y - p0    * p0;     sum += b0.x * d * d;
        d = xv0.z - xv0.y * xv0.y;  sum += b0.y * d * d;
        d = xv0.w - xv0.z * xv0.z;  sum += b0.z * d * d;
        d = xv1.x - xv0.w * xv0.w;  sum += b0.w * d * d;
        d = xv1.y - xv1.x * xv1.x;  sum += b1.x * d * d;
        d = xv1.z - xv1.y * xv1.y;  sum += b1.y * d * d;
        d = xv1.w - xv1.z * xv1.z;  sum += b1.z * d * d;
        d = xv2.x - xv1.w * xv1.w;  sum += b1.w * d * d;
        d = xv2.y - xv2.x * xv2.x;  sum += b2.x * d * d;
        d = xv2.z - xv2.y * xv2.y;  sum += b2.y * d * d;
        d = xv2.w - xv2.z * xv2.z;  sum += b2.z * d * d;
        d = xv3.x - xv2.w * xv2.w;  sum += b2.w * d * d;
        d = xv3.y - xv3.x * xv3.x;  sum += b3.x * d * d;
        d = xv3.z - xv3.y * xv3.y;  sum += b3.y * d * d;
        d = xv3.w - xv3.z * xv3.z;  sum += w14 * d * d;
        d = x16   - xv3.w * xv3.w;  sum += w15 * d * d;
    }

    // Warp tree reduce
    #pragma unroll
    for (int off = 16; off > 0; off >>= 1)
        sum += __shfl_xor_sync(0xFFFFFFFFu, sum, off);

    // Block reduce across 8 warps
    __shared__ float s[THREADS / 32];
    __shared__ bool  s_last;
    if (lane == 0) s[wid] = sum;
    __syncthreads();
    if (wid == 0) {
        float v = (lane < THREADS / 32) ? s[lane] : 0.0f;
        #pragma unroll
        for (int off = 4; off > 0; off >>= 1)
            v += __shfl_xor_sync(0xFFFFFFFFu, v, off);
        if (lane == 0) {
            g_partials[blockIdx.x] = v;
            __threadfence();
            const unsigned int prev = atomicAdd(&g_count, 1u);
            s_last = (prev == GBLOCKS - 1);
        }
    }
    __syncthreads();

    // Last-arriving block: deterministic final reduction (fixed order).
    if (s_last) {
        float v = 0.0f;
        for (int t = tid; t < GBLOCKS; t += THREADS)
            v += g_partials[t];

        #pragma unroll
        for (int off = 16; off > 0; off >>= 1)
            v += __shfl_xor_sync(0xFFFFFFFFu, v, off);

        if (lane == 0) s[wid] = v;
        __syncthreads();
        if (wid == 0) {
            float w = (lane < THREADS / 32) ? s[lane] : 0.0f;
            #pragma unroll
            for (int off = 4; off > 0; off >>= 1)
                w += __shfl_xor_sync(0xFFFFFFFFu, w, off);
            if (lane == 0) {
                const float dd = x[0] - mu[0];
                out[0] = -a[0] * dd * dd - w;
                g_count = 0;   // reset for next graph replay
            }
        }
    }
}

extern "C" void kernel_launch(void* const* d_in, const int* in_sizes, int n_in,
                              void* d_out, int out_size)
{
    const float* x  = (const float*)d_in[0];
    const float* a  = (const float*)d_in[1];
    const float* b  = (const float*)d_in[2];
    const float* mu = (const float*)d_in[3];
    float* out = (float*)d_out;

    rosen_fused_kernel<<<GBLOCKS, THREADS>>>(x, a, b, mu, out);
}

// round 8
// speedup vs baseline: 1.2432x; 1.2432x over previous
#include <cuda_runtime.h>
#include <cuda_bf16.h>

// Problem constants
#define N1M1 4096          // row width of b / y
#define ROWS 8191          // n2 - 1 rows contribute
#define THREADS 256
#define SEG 1024           // segment stride: 4 segments x 256 threads x 4 floats = 4096

__device__ float        g_partials[ROWS];
__device__ unsigned int g_count = 0;

__global__ __launch_bounds__(THREADS)
void rosen_fused_kernel(const float* __restrict__ x,
                        const float* __restrict__ a,
                        const float* __restrict__ b,
                        const float* __restrict__ mu,
                        float* __restrict__ out)
{
    const int tid  = threadIdx.x;
    const int lane = tid & 31;
    const int wid  = tid >> 5;
    const int i    = blockIdx.x;                 // one row per CTA
    const long base = (long)i * N1M1;
    const int  j    = tid << 2;                  // 0..1020 within each segment

    // ---- Front-batched, warp-coalesced loads: 8x LDG.128 (each warp: 512B contiguous)
    float4 xv[4], bv[4];
    #pragma unroll
    for (int s = 0; s < 4; s++) {
        xv[s] = __ldcs(reinterpret_cast<const float4*>(x + base + s * SEG + j));
        bv[s] = __ldcs(reinterpret_cast<const float4*>(b + base + s * SEG + j));
    }
    // Lane-31 boundary scalars: x[base + s*SEG + j + 4] (predicated; 1 load/warp/seg).
    float nxt[4];
    #pragma unroll
    for (int s = 0; s < 4; s++)
        nxt[s] = (lane == 31) ? __ldcs(x + base + s * SEG + j + 4) : 0.0f;
    // Roll-wrap value for col 0 (tid 0 only): y_prev[i,0] = x[base + 4096].
    const float xwrp = (tid == 0) ? __ldcs(x + base + N1M1) : 0.0f;

    // ---- cur[3] via neighbor-lane shuffle (lane 31 uses its scalar load)
    float c3[4];
    #pragma unroll
    for (int s = 0; s < 4; s++) {
        float v = __shfl_sync(0xFFFFFFFFu, xv[s].x, (lane + 1) & 31);
        c3[s] = (lane == 31) ? nxt[s] : v;
    }

    // ---- Math: 16 terms
    float sum = 0.0f;
    #pragma unroll
    for (int s = 0; s < 4; s++) {
        float p0 = xv[s].x;
        if (s == 0 && tid == 0) p0 = xwrp;       // roll wrap at column 0
        float w2 = bv[s].z, w3 = bv[s].w;
        if (s == 3 && tid == THREADS - 1) {      // columns 4094,4095 don't contribute
            w2 = 0.0f; w3 = 0.0f;
        }
        float d;
        d = xv[s].y - p0      * p0;       sum += bv[s].x * d * d;
        d = xv[s].z - xv[s].y * xv[s].y;  sum += bv[s].y * d * d;
        d = xv[s].w - xv[s].z * xv[s].z;  sum += w2      * d * d;
        d = c3[s]   - xv[s].w * xv[s].w;  sum += w3      * d * d;
    }

    // ---- Warp tree reduce
    #pragma unroll
    for (int off = 16; off > 0; off >>= 1)
        sum += __shfl_xor_sync(0xFFFFFFFFu, sum, off);

    // ---- Block reduce across 8 warps
    __shared__ float s_red[THREADS / 32];
    __shared__ bool  s_last;
    if (lane == 0) s_red[wid] = sum;
    __syncthreads();
    if (wid == 0) {
        float v = (lane < THREADS / 32) ? s_red[lane] : 0.0f;
        #pragma unroll
        for (int off = 4; off > 0; off >>= 1)
            v += __shfl_xor_sync(0xFFFFFFFFu, v, off);
        if (lane == 0) {
            g_partials[i] = v;
            __threadfence();
            const unsigned int prev = atomicAdd(&g_count, 1u);
            s_last = (prev == ROWS - 1);
        }
    }
    __syncthreads();

    // ---- Last-arriving block: deterministic final reduction (fixed order).
    if (s_last) {
        float v = 0.0f;
        #pragma unroll 8
        for (int t = tid; t < ROWS; t += THREADS)
            v += g_partials[t];

        #pragma unroll
        for (int off = 16; off > 0; off >>= 1)
            v += __shfl_xor_sync(0xFFFFFFFFu, v, off);

        if (lane == 0) s_red[wid] = v;
        __syncthreads();
        if (wid == 0) {
            float w = (lane < THREADS / 32) ? s_red[lane] : 0.0f;
            #pragma unroll
            for (int off = 4; off > 0; off >>= 1)
                w += __shfl_xor_sync(0xFFFFFFFFu, w, off);
            if (lane == 0) {
                const float dd = x[0] - mu[0];
                out[0] = -a[0] * dd * dd - w;
                g_count = 0;   // reset for next graph replay
            }
        }
    }
}

extern "C" void kernel_launch(void* const* d_in, const int* in_sizes, int n_in,
                              void* d_out, int out_size)
{
    const float* x  = (const float*)d_in[0];
    const float* a  = (const float*)d_in[1];
    const float* b  = (const float*)d_in[2];
    const float* mu = (const float*)d_in[3];
    float* out = (float*)d_out;

    rosen_fused_kernel<<<ROWS, THREADS>>>(x, a, b, mu, out);
}

// round 9
// speedup vs baseline: 1.3355x; 1.0742x over previous
#include <cuda_runtime.h>
#include <cuda_bf16.h>

// Problem constants
#define N1M1 4096          // row width of b / y
#define ROWS 8191          // n2 - 1 rows contribute
#define THREADS 256
#define SEG 1024           // 4 segments x 256 threads x 4 floats = 4096 columns
#define GBLOCKS 1184       // 148 SMs x 8 CTAs -> single wave

__device__ float        g_partials[GBLOCKS];
__device__ unsigned int g_count = 0;

__global__ __launch_bounds__(THREADS)
void rosen_fused_kernel(const float* __restrict__ x,
                        const float* __restrict__ a,
                        const float* __restrict__ b,
                        const float* __restrict__ mu,
                        float* __restrict__ out)
{
    const int tid  = threadIdx.x;
    const int lane = tid & 31;
    const int wid  = tid >> 5;
    const int j    = tid << 2;                   // 0..1020 within each segment

    float sum = 0.0f;

    // Grid-stride over rows: one full row per iteration.
    // 8 front-batched, warp-coalesced LDG.128 (each warp: 512B contiguous).
    for (int i = blockIdx.x; i < ROWS; i += GBLOCKS) {
        const long base = (long)i * N1M1;

        float4 xv[4], bv[4];
        #pragma unroll
        for (int s = 0; s < 4; s++) {
            xv[s] = *reinterpret_cast<const float4*>(x + base + s * SEG + j);
            bv[s] = *reinterpret_cast<const float4*>(b + base + s * SEG + j);
        }
        // Lane-31 boundary scalars (1 predicated load/warp/segment, mostly L1/L2 hits).
        float nxt[4];
        #pragma unroll
        for (int s = 0; s < 4; s++)
            nxt[s] = (lane == 31) ? x[base + s * SEG + j + 4] : 0.0f;
        // Roll wrap (tid 0 only): y_prev[i,0] = x[base + 4096].
        const float xwrp = (tid == 0) ? x[base + N1M1] : 0.0f;

        // cur[3] via neighbor-lane shuffle; lane 31 uses its scalar load.
        float c3[4];
        #pragma unroll
        for (int s = 0; s < 4; s++) {
            const float v = __shfl_sync(0xFFFFFFFFu, xv[s].x, (lane + 1) & 31);
            c3[s] = (lane == 31) ? nxt[s] : v;
        }

        #pragma unroll
        for (int s = 0; s < 4; s++) {
            float p0 = xv[s].x;
            if (s == 0 && tid == 0) p0 = xwrp;           // roll wrap at column 0
            float w2 = bv[s].z, w3 = bv[s].w;
            if (s == 3 && tid == THREADS - 1) {          // cols 4094,4095 excluded
                w2 = 0.0f; w3 = 0.0f;
            }
            float d;
            d = xv[s].y - p0      * p0;       sum += bv[s].x * d * d;
            d = xv[s].z - xv[s].y * xv[s].y;  sum += bv[s].y * d * d;
            d = xv[s].w - xv[s].z * xv[s].z;  sum += w2      * d * d;
            d = c3[s]   - xv[s].w * xv[s].w;  sum += w3      * d * d;
        }
    }

    // Warp tree reduce
    #pragma unroll
    for (int off = 16; off > 0; off >>= 1)
        sum += __shfl_xor_sync(0xFFFFFFFFu, sum, off);

    // Block reduce across 8 warps
    __shared__ float s_red[THREADS / 32];
    __shared__ bool  s_last;
    if (lane == 0) s_red[wid] = sum;
    __syncthreads();
    if (wid == 0) {
        float v = (lane < THREADS / 32) ? s_red[lane] : 0.0f;
        #pragma unroll
        for (int off = 4; off > 0; off >>= 1)
            v += __shfl_xor_sync(0xFFFFFFFFu, v, off);
        if (lane == 0) {
            g_partials[blockIdx.x] = v;
            // acq_rel atomic: release orders the partial store (no CCTL.IVALL
            // L1-flush like __threadfence); acquire orders the last block's reads.
            unsigned int prev;
            asm volatile("atom.acq_rel.gpu.global.add.u32 %0, [%1], %2;"
                         : "=r"(prev)
                         : "l"(&g_count), "r"(1u)
                         : "memory");
            s_last = (prev == GBLOCKS - 1);
        }
    }
    __syncthreads();

    // Last-arriving block: deterministic final reduction (fixed order).
    if (s_last) {
        float v = 0.0f;
        #pragma unroll
        for (int t = tid; t < GBLOCKS; t += THREADS)   // 5 rounds (1184/256)
            v += __ldcg(&g_partials[t]);               // L2-direct, no stale L1

        #pragma unroll
        for (int off = 16; off > 0; off >>= 1)
            v += __shfl_xor_sync(0xFFFFFFFFu, v, off);

        if (lane == 0) s_red[wid] = v;
        __syncthreads();
        if (wid == 0) {
            float w = (lane < THREADS / 32) ? s_red[lane] : 0.0f;
            #pragma unroll
            for (int off = 4; off > 0; off >>= 1)
                w += __shfl_xor_sync(0xFFFFFFFFu, w, off);
            if (lane == 0) {
                const float dd = x[0] - mu[0];
                out[0] = -a[0] * dd * dd - w;
                g_count = 0;   // reset for next graph replay
            }
        }
    }
}

extern "C" void kernel_launch(void* const* d_in, const int* in_sizes, int n_in,
                              void* d_out, int out_size)
{
    const float* x  = (const float*)d_in[0];
    const float* a  = (const float*)d_in[1];
    const float* b  = (const float*)d_in[2];
    const float* mu = (const float*)d_in[3];
    float* out = (float*)d_out;

    rosen_fused_kernel<<<GBLOCKS, THREADS>>>(x, a, b, mu, out);
}